// round 5
// baseline (speedup 1.0000x reference)
#include <cuda_runtime.h>
#include <stdint.h>
#include <math.h>

#define BB   256
#define NT   196
#define NP   208              // NT padded to 13*16
#define DIM  384
#define HH   12
#define KD   32
#define VD   32
#define MM   (BB*NT)          // 50176
#define FF   (HH*(2*KD+VD))   // 1152
#define QK_SCALE 0.17677669529663687f  // 32^-0.5

// ---------------- scratch (static device arrays; no cudaMalloc) ---------------
__device__ uint32_t g_xn   [MM*DIM];        // LN output, tf32 bits
__device__ uint32_t g_q32  [BB*HH*NT*KD];   // q*scale, tf32 bits
__device__ uint32_t g_k32  [BB*HH*NT*KD];
__device__ uint32_t g_v32  [BB*HH*NT*VD];
__device__ uint32_t g_att32[MM*DIM];        // attention out, tf32 bits
__device__ float    g_b    [HH*NP*NP];      // expanded bias, pad = -1e30
__device__ uint32_t g_qkvw32 [FF*DIM];      // weights, tf32 bits
__device__ uint32_t g_projw32[DIM*DIM];

// ---------------- helpers -----------------------------------------------------
__device__ __forceinline__ uint32_t f2tf32(float f) {
    uint32_t u;
    asm("cvt.rna.tf32.f32 %0, %1;" : "=r"(u) : "f"(f));
    return u;
}
__device__ __forceinline__ void mma_tf32(float* c, const uint32_t* a, const uint32_t* b) {
    asm volatile(
        "mma.sync.aligned.m16n8k8.row.col.f32.tf32.tf32.f32 "
        "{%0,%1,%2,%3}, {%4,%5,%6,%7}, {%8,%9}, {%0,%1,%2,%3};"
        : "+f"(c[0]), "+f"(c[1]), "+f"(c[2]), "+f"(c[3])
        : "r"(a[0]), "r"(a[1]), "r"(a[2]), "r"(a[3]), "r"(b[0]), "r"(b[1]));
}
__device__ __forceinline__ void cp_async16(uint32_t saddr, const void* gptr) {
    asm volatile("cp.async.ca.shared.global [%0], [%1], 16;\n" :: "r"(saddr), "l"(gptr));
}

// ---------------- kernel 0: convert weights to tf32 bits ----------------------
__global__ void cvt_tf32_kernel(const float* __restrict__ in, uint32_t* __restrict__ out, int n) {
    int i = blockIdx.x * 256 + threadIdx.x;
    if (i < n) out[i] = f2tf32(in[i]);
}

// ---------------- kernel 1: LayerNorm -> tf32 bits ----------------------------
__global__ void __launch_bounds__(256) ln_kernel(const float* __restrict__ x,
                                                 const float* __restrict__ w,
                                                 const float* __restrict__ b) {
    int row  = blockIdx.x * 8 + (threadIdx.x >> 5);
    int lane = threadIdx.x & 31;
    const float* xr = x + (size_t)row * DIM;
    float4 v[3];
    float sum = 0.f, sq = 0.f;
#pragma unroll
    for (int j = 0; j < 3; j++) {
        v[j] = *(const float4*)(xr + j*128 + lane*4);
        sum += v[j].x + v[j].y + v[j].z + v[j].w;
        sq  += v[j].x*v[j].x + v[j].y*v[j].y + v[j].z*v[j].z + v[j].w*v[j].w;
    }
#pragma unroll
    for (int o = 16; o; o >>= 1) {
        sum += __shfl_xor_sync(0xffffffffu, sum, o);
        sq  += __shfl_xor_sync(0xffffffffu, sq,  o);
    }
    float mean = sum * (1.f/DIM);
    float var  = sq  * (1.f/DIM) - mean*mean;
    float inv  = rsqrtf(var + 1e-5f);
    uint32_t* orow = g_xn + (size_t)row * DIM;
#pragma unroll
    for (int j = 0; j < 3; j++) {
        float4 ww = *(const float4*)(w + j*128 + lane*4);
        float4 bb = *(const float4*)(b + j*128 + lane*4);
        uint4 o4;
        o4.x = f2tf32((v[j].x - mean)*inv*ww.x + bb.x);
        o4.y = f2tf32((v[j].y - mean)*inv*ww.y + bb.y);
        o4.z = f2tf32((v[j].z - mean)*inv*ww.z + bb.z);
        o4.w = f2tf32((v[j].w - mean)*inv*ww.w + bb.w);
        *(uint4*)(orow + j*128 + lane*4) = o4;
    }
}

// ---------------- bias expansion: gb[h][n][m] ---------------------------------
__global__ void bias_expand(const float* __restrict__ ab, const int* __restrict__ bidx) {
    int n = blockIdx.x, h = blockIdx.y, m = threadIdx.x;
    float v = -1e30f;
    if (n < NT && m < NT) v = ab[h*NT + bidx[n*NT + m]];
    g_b[((size_t)h*NP + n)*NP + m] = v;
}

// ---------------- kernel 2/4: TF32 GEMM, 128x128, 3-stage cp.async ------------
template<bool QKV>
__global__ void __launch_bounds__(256) gemm_tf32(const uint32_t* __restrict__ W,
                                                 const float* __restrict__ bias,
                                                 float* __restrict__ C) {
    extern __shared__ uint32_t sm[];
    // 3 stages, each: A[128][36] followed by B[128][36]
    const int STG = 128*36*2;
    const uint32_t* A = QKV ? g_xn : g_att32;

    int tid  = threadIdx.x;
    int wid  = tid >> 5, lane = tid & 31;
    int warp_m = (wid >> 1) * 32;   // 0,32,64,96
    int warp_n = (wid & 1) * 64;    // 0,64
    int col0 = blockIdx.x * 128;
    int row0 = blockIdx.y * 128;

    int lr = tid >> 3;              // 0..31
    int lc = tid & 7;
    uint32_t sBase = (uint32_t)__cvta_generic_to_shared(sm);

    float acc[2][8][4];
#pragma unroll
    for (int i = 0; i < 2; i++)
#pragma unroll
        for (int j = 0; j < 8; j++)
#pragma unroll
            for (int k = 0; k < 4; k++) acc[i][j][k] = 0.f;

    auto load_stage = [&](int st, int kt) {
        uint32_t base = sBase + st*STG*4;
#pragma unroll
        for (int it = 0; it < 4; it++) {
            int r = lr + it*32;
            cp_async16(base + (r*36 + lc*4)*4,
                       A + (size_t)(row0 + r)*DIM + kt + lc*4);
            cp_async16(base + ((128 + r)*36 + lc*4)*4,
                       W + (size_t)(col0 + r)*DIM + kt + lc*4);
        }
        asm volatile("cp.async.commit_group;\n" ::);
    };

    const int T = DIM / 32;         // 12
    load_stage(0, 0);
    load_stage(1, 32);

    for (int t = 0; t < T; t++) {
        if (t + 2 < T) {
            load_stage((t+2)%3, (t+2)*32);
            asm volatile("cp.async.wait_group 2;\n" ::);
        } else if (t + 1 < T) {
            asm volatile("cp.async.wait_group 1;\n" ::);
        } else {
            asm volatile("cp.async.wait_group 0;\n" ::);
        }
        __syncthreads();
        const uint32_t* Ab = sm + (t%3)*STG;
        const uint32_t* Bb = Ab + 128*36;
#pragma unroll
        for (int ks = 0; ks < 4; ks++) {
            int kq = ks*8 + (lane & 3);
            uint32_t af[2][4], bf[8][2];
#pragma unroll
            for (int mt = 0; mt < 2; mt++) {
                int r = warp_m + mt*16 + (lane >> 2);
                af[mt][0] = Ab[(r   )*36 + kq];
                af[mt][1] = Ab[(r+8 )*36 + kq];
                af[mt][2] = Ab[(r   )*36 + kq+4];
                af[mt][3] = Ab[(r+8 )*36 + kq+4];
            }
#pragma unroll
            for (int nt = 0; nt < 8; nt++) {
                int c = warp_n + nt*8 + (lane >> 2);
                bf[nt][0] = Bb[c*36 + kq];
                bf[nt][1] = Bb[c*36 + kq+4];
            }
#pragma unroll
            for (int mt = 0; mt < 2; mt++)
#pragma unroll
                for (int nt = 0; nt < 8; nt++)
                    mma_tf32(acc[mt][nt], af[mt], bf[nt]);
        }
        __syncthreads();
    }

#pragma unroll
    for (int mt = 0; mt < 2; mt++) {
#pragma unroll
        for (int nt = 0; nt < 8; nt++) {
#pragma unroll
            for (int i = 0; i < 4; i++) {
                int m  = row0 + warp_m + mt*16 + (lane >> 2) + ((i >> 1) * 8);
                int nn = col0 + warp_n + nt*8 + (lane & 3)*2 + (i & 1);
                float val = acc[mt][nt][i] + bias[nn];
                if (QKV) {
                    int b_ = m / NT, n_ = m - b_*NT;
                    int h  = nn / 96, c = nn - h*96;
                    size_t base = ((size_t)(b_*HH + h)*NT + n_);
                    if      (c < KD)   g_q32[base*KD + c]        = f2tf32(val * QK_SCALE);
                    else if (c < 2*KD) g_k32[base*KD + (c-KD)]   = f2tf32(val);
                    else               g_v32[base*VD + (c-2*KD)] = f2tf32(val);
                } else {
                    C[(size_t)m*DIM + nn] = val;
                }
            }
        }
    }
}

// ---------------- kernel 3: flash tensor-core attention (no-max softmax) ------
// Scores are bounded (|s| ~ 2): exp needs no max shift -> no reductions for max,
// no online rescaling. Pad cols carry -1e30 -> exp = 0. 2 col chunks keep regs low.
#define VT_PITCH 212
__global__ void __launch_bounds__(224, 2) attn_mma() {
    extern __shared__ uint32_t smu[];
    uint32_t* Ksh = smu;                 // [208][36] tf32 bits
    uint32_t* Vt  = smu + NP*36;         // [32][212] tf32 bits, token-permuted

    int bh = blockIdx.x;
    int b_ = bh / HH;
    int h  = bh - b_*HH;
    int tid = threadIdx.x, w = tid >> 5, lane = tid & 31;

    for (int i = tid; i < NP*8; i += 224) {
        int m = i >> 3, c4 = i & 7;
        uint4 kv = {0u,0u,0u,0u};
        if (m < NT) kv = *(const uint4*)(g_k32 + ((size_t)bh*NT + m)*KD + c4*4);
        *(uint4*)&Ksh[m*36 + c4*4] = kv;

        int p = m;
        int tok = (p & ~7) + 2*(p & 3) + ((p >> 2) & 1);
        uint4 vv = {0u,0u,0u,0u};
        if (tok < NT) vv = *(const uint4*)(g_v32 + ((size_t)bh*NT + tok)*VD + c4*4);
        Vt[(c4*4+0)*VT_PITCH + p] = vv.x;
        Vt[(c4*4+1)*VT_PITCH + p] = vv.y;
        Vt[(c4*4+2)*VT_PITCH + p] = vv.z;
        Vt[(c4*4+3)*VT_PITCH + p] = vv.w;
    }
    __syncthreads();

    for (int iter = 0; iter < 2; iter++) {
        int tile = w + iter*7;
        if (tile >= 13) break;
        int r0 = tile*16 + (lane >> 2);
        int r1 = r0 + 8;

        uint32_t qa[4][4];
        const uint32_t* q0p = g_q32 + ((size_t)bh*NT + r0)*KD;
        const uint32_t* q1p = g_q32 + ((size_t)bh*NT + r1)*KD;
#pragma unroll
        for (int kt = 0; kt < 4; kt++) {
            int k0 = kt*8 + (lane & 3);
            qa[kt][0] = (r0 < NT) ? q0p[k0    ] : 0u;
            qa[kt][1] = (r1 < NT) ? q1p[k0    ] : 0u;
            qa[kt][2] = (r0 < NT) ? q0p[k0 + 4] : 0u;
            qa[kt][3] = (r1 < NT) ? q1p[k0 + 4] : 0u;
        }

        const float* gb0 = g_b + ((size_t)h*NP + r0)*NP;
        const float* gb1 = g_b + ((size_t)h*NP + r1)*NP;

        float l0 = 0.f, l1 = 0.f;
        float o[4][4];
#pragma unroll
        for (int vt = 0; vt < 4; vt++) { o[vt][0]=0.f; o[vt][1]=0.f; o[vt][2]=0.f; o[vt][3]=0.f; }

#pragma unroll
        for (int ch = 0; ch < 2; ch++) {
            int cb = ch * 104;
            float s[13][4];
#pragma unroll
            for (int nt = 0; nt < 13; nt++) { s[nt][0]=0.f; s[nt][1]=0.f; s[nt][2]=0.f; s[nt][3]=0.f; }
#pragma unroll
            for (int nt = 0; nt < 13; nt++) {
                int c = cb + nt*8 + (lane >> 2);
#pragma unroll
                for (int kt = 0; kt < 4; kt++) {
                    uint32_t bfr[2];
                    bfr[0] = Ksh[c*36 + kt*8 + (lane & 3)];
                    bfr[1] = Ksh[c*36 + kt*8 + (lane & 3) + 4];
                    mma_tf32(s[nt], qa[kt], bfr);
                }
            }
            // exp(s + bias), accumulate row sums (no max shift needed)
#pragma unroll
            for (int nt = 0; nt < 13; nt++) {
                int cc = cb + nt*8 + 2*(lane & 3);
                float2 b0 = *(const float2*)(gb0 + cc);
                float2 b1 = *(const float2*)(gb1 + cc);
                s[nt][0] = __expf(s[nt][0] + b0.x); l0 += s[nt][0];
                s[nt][1] = __expf(s[nt][1] + b0.y); l0 += s[nt][1];
                s[nt][2] = __expf(s[nt][2] + b1.x); l1 += s[nt][2];
                s[nt][3] = __expf(s[nt][3] + b1.y); l1 += s[nt][3];
            }
            // O += P V (P C-frag -> A-frag via V token permutation)
#pragma unroll
            for (int kt = 0; kt < 13; kt++) {
                uint32_t pa[4];
                pa[0] = f2tf32(s[kt][0]);
                pa[1] = f2tf32(s[kt][2]);
                pa[2] = f2tf32(s[kt][1]);
                pa[3] = f2tf32(s[kt][3]);
#pragma unroll
                for (int vt = 0; vt < 4; vt++) {
                    uint32_t bfr[2];
                    int d = vt*8 + (lane >> 2);
                    bfr[0] = Vt[d*VT_PITCH + cb + kt*8 + (lane & 3)];
                    bfr[1] = Vt[d*VT_PITCH + cb + kt*8 + (lane & 3) + 4];
                    mma_tf32(o[vt], pa, bfr);
                }
            }
        }

        // row-sum reduction across quad lanes
        l0 += __shfl_xor_sync(0xffffffffu, l0, 1);
        l0 += __shfl_xor_sync(0xffffffffu, l0, 2);
        l1 += __shfl_xor_sync(0xffffffffu, l1, 1);
        l1 += __shfl_xor_sync(0xffffffffu, l1, 2);
        float inv0 = __fdividef(1.f, l0);
        float inv1 = __fdividef(1.f, l1);

        if (r0 < NT) {
            uint32_t* orow = g_att32 + ((size_t)(b_*NT + r0))*DIM + h*VD;
#pragma unroll
            for (int vt = 0; vt < 4; vt++) {
                orow[vt*8 + 2*(lane & 3)    ] = f2tf32(o[vt][0]*inv0);
                orow[vt*8 + 2*(lane & 3) + 1] = f2tf32(o[vt][1]*inv0);
            }
        }
        if (r1 < NT) {
            uint32_t* orow = g_att32 + ((size_t)(b_*NT + r1))*DIM + h*VD;
#pragma unroll
            for (int vt = 0; vt < 4; vt++) {
                orow[vt*8 + 2*(lane & 3)    ] = f2tf32(o[vt][2]*inv1);
                orow[vt*8 + 2*(lane & 3) + 1] = f2tf32(o[vt][3]*inv1);
            }
        }
    }
}

// ---------------- launch ------------------------------------------------------
extern "C" void kernel_launch(void* const* d_in, const int* in_sizes, int n_in,
                              void* d_out, int out_size) {
    const float* x      = (const float*)d_in[0];
    const float* norm_w = (const float*)d_in[1];
    const float* norm_b = (const float*)d_in[2];
    const float* qkv_w  = (const float*)d_in[3];
    const float* qkv_b  = (const float*)d_in[4];
    const float* attb   = (const float*)d_in[5];
    const float* proj_w = (const float*)d_in[6];
    const float* proj_b = (const float*)d_in[7];
    const int*   bidx   = (const int*)  d_in[8];
    float* out = (float*)d_out;

    uint32_t* qkvw32;  cudaGetSymbolAddress((void**)&qkvw32,  g_qkvw32);
    uint32_t* projw32; cudaGetSymbolAddress((void**)&projw32, g_projw32);

    const int gemm_smem = 3 * 2 * 128 * 36 * (int)sizeof(uint32_t);       // 110592
    const int attn_smem = (NP*36 + 32*VT_PITCH) * (int)sizeof(uint32_t);  // 57088
    cudaFuncSetAttribute(gemm_tf32<true >, cudaFuncAttributeMaxDynamicSharedMemorySize, gemm_smem);
    cudaFuncSetAttribute(gemm_tf32<false>, cudaFuncAttributeMaxDynamicSharedMemorySize, gemm_smem);
    cudaFuncSetAttribute(attn_mma,         cudaFuncAttributeMaxDynamicSharedMemorySize, attn_smem);

    cvt_tf32_kernel<<<(FF*DIM + 255)/256,  256>>>(qkv_w,  qkvw32,  FF*DIM);
    cvt_tf32_kernel<<<(DIM*DIM + 255)/256, 256>>>(proj_w, projw32, DIM*DIM);
    ln_kernel<<<MM/8, 256>>>(x, norm_w, norm_b);
    bias_expand<<<dim3(NP, HH), NP>>>(attb, bidx);
    gemm_tf32<true ><<<dim3(FF/128,  MM/128), 256, gemm_smem>>>(qkvw32, qkv_b, nullptr);
    attn_mma<<<BB*HH, 224, attn_smem>>>();
    gemm_tf32<false><<<dim3(DIM/128, MM/128), 256, gemm_smem>>>(projw32, proj_b, out);
}

// round 6
// speedup vs baseline: 1.1233x; 1.1233x over previous
#include <cuda_runtime.h>
#include <stdint.h>
#include <math.h>

#define BB   256
#define NT   196
#define NP   208              // NT padded to 13*16
#define DIM  384
#define HH   12
#define KD   32
#define VD   32
#define MM   (BB*NT)          // 50176
#define FF   (HH*(2*KD+VD))   // 1152
#define QK_SCALE 0.17677669529663687f  // 32^-0.5

// ---------------- scratch (static device arrays; no cudaMalloc) ---------------
__device__ uint32_t g_xn   [MM*DIM];        // LN output, tf32 bits
__device__ uint32_t g_q32  [BB*HH*NT*KD];   // q*scale, tf32 bits
__device__ uint32_t g_k32  [BB*HH*NT*KD];
__device__ uint32_t g_v32  [BB*HH*NT*VD];
__device__ uint32_t g_att32[MM*DIM];        // attention out, tf32 bits
__device__ float    g_b    [HH*NP*NP];      // expanded bias, pad = -1e30
__device__ uint32_t g_qkvw32 [FF*DIM];      // weights, tf32 bits
__device__ uint32_t g_projw32[DIM*DIM];

// ---------------- helpers -----------------------------------------------------
__device__ __forceinline__ uint32_t f2tf32(float f) {
    uint32_t u;
    asm("cvt.rna.tf32.f32 %0, %1;" : "=r"(u) : "f"(f));
    return u;
}
__device__ __forceinline__ void mma_tf32(float* c, const uint32_t* a, const uint32_t* b) {
    asm volatile(
        "mma.sync.aligned.m16n8k8.row.col.f32.tf32.tf32.f32 "
        "{%0,%1,%2,%3}, {%4,%5,%6,%7}, {%8,%9}, {%0,%1,%2,%3};"
        : "+f"(c[0]), "+f"(c[1]), "+f"(c[2]), "+f"(c[3])
        : "r"(a[0]), "r"(a[1]), "r"(a[2]), "r"(a[3]), "r"(b[0]), "r"(b[1]));
}
__device__ __forceinline__ void cp_async16(uint32_t saddr, const void* gptr) {
    asm volatile("cp.async.ca.shared.global [%0], [%1], 16;\n" :: "r"(saddr), "l"(gptr));
}

// ---------------- kernel 0: convert weights to tf32 bits ----------------------
__global__ void cvt_tf32_kernel(const float* __restrict__ in, uint32_t* __restrict__ out, int n) {
    int i = blockIdx.x * 256 + threadIdx.x;
    if (i < n) out[i] = f2tf32(in[i]);
}

// ---------------- kernel 1: LayerNorm -> tf32 bits ----------------------------
__global__ void __launch_bounds__(256) ln_kernel(const float* __restrict__ x,
                                                 const float* __restrict__ w,
                                                 const float* __restrict__ b) {
    int row  = blockIdx.x * 8 + (threadIdx.x >> 5);
    int lane = threadIdx.x & 31;
    const float* xr = x + (size_t)row * DIM;
    float4 v[3];
    float sum = 0.f, sq = 0.f;
#pragma unroll
    for (int j = 0; j < 3; j++) {
        v[j] = *(const float4*)(xr + j*128 + lane*4);
        sum += v[j].x + v[j].y + v[j].z + v[j].w;
        sq  += v[j].x*v[j].x + v[j].y*v[j].y + v[j].z*v[j].z + v[j].w*v[j].w;
    }
#pragma unroll
    for (int o = 16; o; o >>= 1) {
        sum += __shfl_xor_sync(0xffffffffu, sum, o);
        sq  += __shfl_xor_sync(0xffffffffu, sq,  o);
    }
    float mean = sum * (1.f/DIM);
    float var  = sq  * (1.f/DIM) - mean*mean;
    float inv  = rsqrtf(var + 1e-5f);
    uint32_t* orow = g_xn + (size_t)row * DIM;
#pragma unroll
    for (int j = 0; j < 3; j++) {
        float4 ww = *(const float4*)(w + j*128 + lane*4);
        float4 bb = *(const float4*)(b + j*128 + lane*4);
        uint4 o4;
        o4.x = f2tf32((v[j].x - mean)*inv*ww.x + bb.x);
        o4.y = f2tf32((v[j].y - mean)*inv*ww.y + bb.y);
        o4.z = f2tf32((v[j].z - mean)*inv*ww.z + bb.z);
        o4.w = f2tf32((v[j].w - mean)*inv*ww.w + bb.w);
        *(uint4*)(orow + j*128 + lane*4) = o4;
    }
}

// ---------------- bias expansion: gb[h][n][m] ---------------------------------
__global__ void bias_expand(const float* __restrict__ ab, const int* __restrict__ bidx) {
    int n = blockIdx.x, h = blockIdx.y, m = threadIdx.x;
    float v = -1e30f;
    if (n < NT && m < NT) v = ab[h*NT + bidx[n*NT + m]];
    g_b[((size_t)h*NP + n)*NP + m] = v;
}

// ---------------- kernel 2/4: TF32 GEMM, 128x128, 2-stage cp.async ------------
// (2-stage = 73.7KB smem -> 2 blocks/SM; 3-stage was a measured regression)
template<bool QKV>
__global__ void __launch_bounds__(256) gemm_tf32(const uint32_t* __restrict__ W,
                                                 const float* __restrict__ bias,
                                                 float* __restrict__ C) {
    extern __shared__ uint32_t sm[];
    uint32_t* As = sm;                 // [2][128][36]
    uint32_t* Bs = sm + 2*128*36;      // [2][128][36]
    const uint32_t* A = QKV ? g_xn : g_att32;

    int tid  = threadIdx.x;
    int wid  = tid >> 5, lane = tid & 31;
    int warp_m = (wid >> 1) * 32;   // 0,32,64,96
    int warp_n = (wid & 1) * 64;    // 0,64
    int col0 = blockIdx.x * 128;
    int row0 = blockIdx.y * 128;

    int lr = tid >> 3;              // 0..31
    int lc = tid & 7;
    uint32_t sA = (uint32_t)__cvta_generic_to_shared(As);
    uint32_t sB = (uint32_t)__cvta_generic_to_shared(Bs);

    float acc[2][8][4];
#pragma unroll
    for (int i = 0; i < 2; i++)
#pragma unroll
        for (int j = 0; j < 8; j++)
#pragma unroll
            for (int k = 0; k < 4; k++) acc[i][j][k] = 0.f;

    auto load_stage = [&](int st, int kt) {
#pragma unroll
        for (int it = 0; it < 4; it++) {
            int r = lr + it*32;
            cp_async16(sA + ((st*128 + r)*36 + lc*4)*4,
                       A + (size_t)(row0 + r)*DIM + kt + lc*4);
            cp_async16(sB + ((st*128 + r)*36 + lc*4)*4,
                       W + (size_t)(col0 + r)*DIM + kt + lc*4);
        }
    };

    const int T = DIM / 32;         // 12
    load_stage(0, 0);
    asm volatile("cp.async.commit_group;\n" ::);

    for (int t = 0; t < T; t++) {
        if (t + 1 < T) {
            load_stage((t+1)&1, (t+1)*32);
            asm volatile("cp.async.commit_group;\n" ::);
            asm volatile("cp.async.wait_group 1;\n" ::);
        } else {
            asm volatile("cp.async.wait_group 0;\n" ::);
        }
        __syncthreads();
        int st = t & 1;
        const uint32_t* Ab = As + st*128*36;
        const uint32_t* Bb = Bs + st*128*36;
#pragma unroll
        for (int ks = 0; ks < 4; ks++) {
            int kq = ks*8 + (lane & 3);
            uint32_t af[2][4], bf[8][2];
#pragma unroll
            for (int mt = 0; mt < 2; mt++) {
                int r = warp_m + mt*16 + (lane >> 2);
                af[mt][0] = Ab[(r   )*36 + kq];
                af[mt][1] = Ab[(r+8 )*36 + kq];
                af[mt][2] = Ab[(r   )*36 + kq+4];
                af[mt][3] = Ab[(r+8 )*36 + kq+4];
            }
#pragma unroll
            for (int nt = 0; nt < 8; nt++) {
                int c = warp_n + nt*8 + (lane >> 2);
                bf[nt][0] = Bb[c*36 + kq];
                bf[nt][1] = Bb[c*36 + kq+4];
            }
#pragma unroll
            for (int mt = 0; mt < 2; mt++)
#pragma unroll
                for (int nt = 0; nt < 8; nt++)
                    mma_tf32(acc[mt][nt], af[mt], bf[nt]);
        }
        __syncthreads();
    }

#pragma unroll
    for (int mt = 0; mt < 2; mt++) {
#pragma unroll
        for (int nt = 0; nt < 8; nt++) {
#pragma unroll
            for (int i = 0; i < 4; i++) {
                int m  = row0 + warp_m + mt*16 + (lane >> 2) + ((i >> 1) * 8);
                int nn = col0 + warp_n + nt*8 + (lane & 3)*2 + (i & 1);
                float val = acc[mt][nt][i] + bias[nn];
                if (QKV) {
                    int b_ = m / NT, n_ = m - b_*NT;
                    int h  = nn / 96, c = nn - h*96;
                    size_t base = ((size_t)(b_*HH + h)*NT + n_);
                    if      (c < KD)   g_q32[base*KD + c]        = f2tf32(val * QK_SCALE);
                    else if (c < 2*KD) g_k32[base*KD + (c-KD)]   = f2tf32(val);
                    else               g_v32[base*VD + (c-2*KD)] = f2tf32(val);
                } else {
                    C[(size_t)m*DIM + nn] = val;
                }
            }
        }
    }
}

// ---------------- kernel 3: flash tensor-core attention (no-max softmax) ------
// Scores are bounded (|s| ~ 2): exp needs no max shift. Pad cols = -1e30 -> 0.
#define VT_PITCH 212
__global__ void __launch_bounds__(224, 2) attn_mma() {
    extern __shared__ uint32_t smu[];
    uint32_t* Ksh = smu;                 // [208][36] tf32 bits
    uint32_t* Vt  = smu + NP*36;         // [32][212] tf32 bits, token-permuted

    int bh = blockIdx.x;
    int b_ = bh / HH;
    int h  = bh - b_*HH;
    int tid = threadIdx.x, w = tid >> 5, lane = tid & 31;

    for (int i = tid; i < NP*8; i += 224) {
        int m = i >> 3, c4 = i & 7;
        uint4 kv = {0u,0u,0u,0u};
        if (m < NT) kv = *(const uint4*)(g_k32 + ((size_t)bh*NT + m)*KD + c4*4);
        *(uint4*)&Ksh[m*36 + c4*4] = kv;

        int p = m;
        int tok = (p & ~7) + 2*(p & 3) + ((p >> 2) & 1);
        uint4 vv = {0u,0u,0u,0u};
        if (tok < NT) vv = *(const uint4*)(g_v32 + ((size_t)bh*NT + tok)*VD + c4*4);
        Vt[(c4*4+0)*VT_PITCH + p] = vv.x;
        Vt[(c4*4+1)*VT_PITCH + p] = vv.y;
        Vt[(c4*4+2)*VT_PITCH + p] = vv.z;
        Vt[(c4*4+3)*VT_PITCH + p] = vv.w;
    }
    __syncthreads();

    for (int iter = 0; iter < 2; iter++) {
        int tile = w + iter*7;
        if (tile >= 13) break;
        int r0 = tile*16 + (lane >> 2);
        int r1 = r0 + 8;

        uint32_t qa[4][4];
        const uint32_t* q0p = g_q32 + ((size_t)bh*NT + r0)*KD;
        const uint32_t* q1p = g_q32 + ((size_t)bh*NT + r1)*KD;
#pragma unroll
        for (int kt = 0; kt < 4; kt++) {
            int k0 = kt*8 + (lane & 3);
            qa[kt][0] = (r0 < NT) ? q0p[k0    ] : 0u;
            qa[kt][1] = (r1 < NT) ? q1p[k0    ] : 0u;
            qa[kt][2] = (r0 < NT) ? q0p[k0 + 4] : 0u;
            qa[kt][3] = (r1 < NT) ? q1p[k0 + 4] : 0u;
        }

        const float* gb0 = g_b + ((size_t)h*NP + r0)*NP;
        const float* gb1 = g_b + ((size_t)h*NP + r1)*NP;

        float l0 = 0.f, l1 = 0.f;
        float o[4][4];
#pragma unroll
        for (int vt = 0; vt < 4; vt++) { o[vt][0]=0.f; o[vt][1]=0.f; o[vt][2]=0.f; o[vt][3]=0.f; }

#pragma unroll
        for (int ch = 0; ch < 2; ch++) {
            int cb = ch * 104;
            float s[13][4];
#pragma unroll
            for (int nt = 0; nt < 13; nt++) { s[nt][0]=0.f; s[nt][1]=0.f; s[nt][2]=0.f; s[nt][3]=0.f; }
#pragma unroll
            for (int nt = 0; nt < 13; nt++) {
                int c = cb + nt*8 + (lane >> 2);
#pragma unroll
                for (int kt = 0; kt < 4; kt++) {
                    uint32_t bfr[2];
                    bfr[0] = Ksh[c*36 + kt*8 + (lane & 3)];
                    bfr[1] = Ksh[c*36 + kt*8 + (lane & 3) + 4];
                    mma_tf32(s[nt], qa[kt], bfr);
                }
            }
            // exp(s + bias), accumulate row sums (no max shift needed)
#pragma unroll
            for (int nt = 0; nt < 13; nt++) {
                int cc = cb + nt*8 + 2*(lane & 3);
                float2 b0 = *(const float2*)(gb0 + cc);
                float2 b1 = *(const float2*)(gb1 + cc);
                s[nt][0] = __expf(s[nt][0] + b0.x); l0 += s[nt][0];
                s[nt][1] = __expf(s[nt][1] + b0.y); l0 += s[nt][1];
                s[nt][2] = __expf(s[nt][2] + b1.x); l1 += s[nt][2];
                s[nt][3] = __expf(s[nt][3] + b1.y); l1 += s[nt][3];
            }
            // O += P V (P C-frag -> A-frag via V token permutation)
#pragma unroll
            for (int kt = 0; kt < 13; kt++) {
                uint32_t pa[4];
                pa[0] = f2tf32(s[kt][0]);
                pa[1] = f2tf32(s[kt][2]);
                pa[2] = f2tf32(s[kt][1]);
                pa[3] = f2tf32(s[kt][3]);
#pragma unroll
                for (int vt = 0; vt < 4; vt++) {
                    uint32_t bfr[2];
                    int d = vt*8 + (lane >> 2);
                    bfr[0] = Vt[d*VT_PITCH + cb + kt*8 + (lane & 3)];
                    bfr[1] = Vt[d*VT_PITCH + cb + kt*8 + (lane & 3) + 4];
                    mma_tf32(o[vt], pa, bfr);
                }
            }
        }

        l0 += __shfl_xor_sync(0xffffffffu, l0, 1);
        l0 += __shfl_xor_sync(0xffffffffu, l0, 2);
        l1 += __shfl_xor_sync(0xffffffffu, l1, 1);
        l1 += __shfl_xor_sync(0xffffffffu, l1, 2);
        float inv0 = __fdividef(1.f, l0);
        float inv1 = __fdividef(1.f, l1);

        if (r0 < NT) {
            uint32_t* orow = g_att32 + ((size_t)(b_*NT + r0))*DIM + h*VD;
#pragma unroll
            for (int vt = 0; vt < 4; vt++) {
                orow[vt*8 + 2*(lane & 3)    ] = f2tf32(o[vt][0]*inv0);
                orow[vt*8 + 2*(lane & 3) + 1] = f2tf32(o[vt][1]*inv0);
            }
        }
        if (r1 < NT) {
            uint32_t* orow = g_att32 + ((size_t)(b_*NT + r1))*DIM + h*VD;
#pragma unroll
            for (int vt = 0; vt < 4; vt++) {
                orow[vt*8 + 2*(lane & 3)    ] = f2tf32(o[vt][2]*inv1);
                orow[vt*8 + 2*(lane & 3) + 1] = f2tf32(o[vt][3]*inv1);
            }
        }
    }
}

// ---------------- launch ------------------------------------------------------
extern "C" void kernel_launch(void* const* d_in, const int* in_sizes, int n_in,
                              void* d_out, int out_size) {
    const float* x      = (const float*)d_in[0];
    const float* norm_w = (const float*)d_in[1];
    const float* norm_b = (const float*)d_in[2];
    const float* qkv_w  = (const float*)d_in[3];
    const float* qkv_b  = (const float*)d_in[4];
    const float* attb   = (const float*)d_in[5];
    const float* proj_w = (const float*)d_in[6];
    const float* proj_b = (const float*)d_in[7];
    const int*   bidx   = (const int*)  d_in[8];
    float* out = (float*)d_out;

    uint32_t* qkvw32;  cudaGetSymbolAddress((void**)&qkvw32,  g_qkvw32);
    uint32_t* projw32; cudaGetSymbolAddress((void**)&projw32, g_projw32);

    const int gemm_smem = 2 * 2 * 128 * 36 * (int)sizeof(uint32_t);       // 73728
    const int attn_smem = (NP*36 + 32*VT_PITCH) * (int)sizeof(uint32_t);  // 57088
    cudaFuncSetAttribute(gemm_tf32<true >, cudaFuncAttributeMaxDynamicSharedMemorySize, gemm_smem);
    cudaFuncSetAttribute(gemm_tf32<false>, cudaFuncAttributeMaxDynamicSharedMemorySize, gemm_smem);
    cudaFuncSetAttribute(attn_mma,         cudaFuncAttributeMaxDynamicSharedMemorySize, attn_smem);

    cvt_tf32_kernel<<<(FF*DIM + 255)/256,  256>>>(qkv_w,  qkvw32,  FF*DIM);
    cvt_tf32_kernel<<<(DIM*DIM + 255)/256, 256>>>(proj_w, projw32, DIM*DIM);
    ln_kernel<<<MM/8, 256>>>(x, norm_w, norm_b);
    bias_expand<<<dim3(NP, HH), NP>>>(attb, bidx);
    gemm_tf32<true ><<<dim3(FF/128,  MM/128), 256, gemm_smem>>>(qkvw32, qkv_b, nullptr);
    attn_mma<<<BB*HH, 224, attn_smem>>>();
    gemm_tf32<false><<<dim3(DIM/128, MM/128), 256, gemm_smem>>>(projw32, proj_b, out);
}

// round 8
// speedup vs baseline: 1.8909x; 1.6834x over previous
#include <cuda_runtime.h>
#include <cuda_fp16.h>
#include <stdint.h>
#include <math.h>

#define BB   256
#define NT   196
#define NP   208              // NT padded to 13*16
#define DIM  384
#define HH   12
#define KD   32
#define VD   32
#define MM   (BB*NT)          // 50176
#define FF   (HH*(2*KD+VD))   // 1152
#define QK_SCALE 0.17677669529663687f  // 32^-0.5

typedef unsigned short u16;

// ---------------- scratch (static device arrays; no cudaMalloc) ---------------
__device__ u16   g_xn16 [MM*DIM];        // LN output, fp16
__device__ u16   g_q16  [BB*HH*NT*KD];   // q*scale, fp16
__device__ u16   g_k16  [BB*HH*NT*KD];
__device__ u16   g_v16  [BB*HH*NT*VD];
__device__ u16   g_att16[MM*DIM];        // attention out, fp16
__device__ float g_b    [HH*NP*NP];      // expanded bias, pad = -1e30
__device__ u16   g_qkvw16 [FF*DIM];      // weights, fp16
__device__ u16   g_projw16[DIM*DIM];

// ---------------- helpers -----------------------------------------------------
__device__ __forceinline__ uint32_t pack2(float lo, float hi) {
    half2 h = __floats2half2_rn(lo, hi);
    return *(uint32_t*)&h;
}
__device__ __forceinline__ void mma_f16(float* c, const uint32_t* a, const uint32_t* b) {
    asm volatile(
        "mma.sync.aligned.m16n8k16.row.col.f32.f16.f16.f32 "
        "{%0,%1,%2,%3}, {%4,%5,%6,%7}, {%8,%9}, {%0,%1,%2,%3};"
        : "+f"(c[0]), "+f"(c[1]), "+f"(c[2]), "+f"(c[3])
        : "r"(a[0]), "r"(a[1]), "r"(a[2]), "r"(a[3]), "r"(b[0]), "r"(b[1]));
}
__device__ __forceinline__ void cp_async16(uint32_t saddr, const void* gptr) {
    asm volatile("cp.async.ca.shared.global [%0], [%1], 16;\n" :: "r"(saddr), "l"(gptr));
}

// ---------------- kernel 0: convert weights to fp16 ---------------------------
__global__ void cvt_f16_kernel(const float* __restrict__ in, u16* __restrict__ out, int n4) {
    int i = blockIdx.x * 256 + threadIdx.x;
    if (i < n4) {
        float4 v = *(const float4*)(in + i*4);
        uint2 o;
        o.x = pack2(v.x, v.y);
        o.y = pack2(v.z, v.w);
        *(uint2*)(out + i*4) = o;
    }
}

// ---------------- kernel 1: LayerNorm -> fp16 ---------------------------------
__global__ void __launch_bounds__(256) ln_kernel(const float* __restrict__ x,
                                                 const float* __restrict__ w,
                                                 const float* __restrict__ b) {
    int row  = blockIdx.x * 8 + (threadIdx.x >> 5);
    int lane = threadIdx.x & 31;
    const float* xr = x + (size_t)row * DIM;
    float4 v[3];
    float sum = 0.f, sq = 0.f;
#pragma unroll
    for (int j = 0; j < 3; j++) {
        v[j] = *(const float4*)(xr + j*128 + lane*4);
        sum += v[j].x + v[j].y + v[j].z + v[j].w;
        sq  += v[j].x*v[j].x + v[j].y*v[j].y + v[j].z*v[j].z + v[j].w*v[j].w;
    }
#pragma unroll
    for (int o = 16; o; o >>= 1) {
        sum += __shfl_xor_sync(0xffffffffu, sum, o);
        sq  += __shfl_xor_sync(0xffffffffu, sq,  o);
    }
    float mean = sum * (1.f/DIM);
    float var  = sq  * (1.f/DIM) - mean*mean;
    float inv  = rsqrtf(var + 1e-5f);
    u16* orow = g_xn16 + (size_t)row * DIM;
#pragma unroll
    for (int j = 0; j < 3; j++) {
        float4 ww = *(const float4*)(w + j*128 + lane*4);
        float4 bb = *(const float4*)(b + j*128 + lane*4);
        uint2 o4;
        o4.x = pack2((v[j].x - mean)*inv*ww.x + bb.x, (v[j].y - mean)*inv*ww.y + bb.y);
        o4.y = pack2((v[j].z - mean)*inv*ww.z + bb.z, (v[j].w - mean)*inv*ww.w + bb.w);
        *(uint2*)(orow + j*128 + lane*4) = o4;
    }
}

// ---------------- bias expansion: gb[h][n][m] ---------------------------------
__global__ void bias_expand(const float* __restrict__ ab, const int* __restrict__ bidx) {
    int n = blockIdx.x, h = blockIdx.y, m = threadIdx.x;
    float v = -1e30f;
    if (n < NT && m < NT) v = ab[h*NT + bidx[n*NT + m]];
    g_b[((size_t)h*NP + n)*NP + m] = v;
}

// ---------------- kernel 2/4: FP16 GEMM, 128x128, k-slab 64, 2-stage ----------
// C[m][nn] = sum_k A[m][k]*W[nn][k] + bias[nn].  smem pitch 36 half2 (144B/row).
#define GP2 36
#define GSTG (2*128*GP2)   // half2 per stage (A then B)
template<bool QKV>
__global__ void __launch_bounds__(256) gemm_f16(const u16* __restrict__ W,
                                                const float* __restrict__ bias,
                                                float* __restrict__ C) {
    extern __shared__ uint32_t sm[];
    const u16* A = QKV ? g_xn16 : g_att16;

    int tid  = threadIdx.x;
    int wid  = tid >> 5, lane = tid & 31;
    int g = lane >> 2, t = lane & 3;
    int warp_m = (wid >> 1) * 32;   // 0,32,64,96
    int warp_n = (wid & 1) * 64;    // 0,64
    int col0 = blockIdx.x * 128;
    int row0 = blockIdx.y * 128;

    int lr = tid >> 3;              // 0..31
    int lc = tid & 7;               // 16B chunk in a 128B data row
    uint32_t sb = (uint32_t)__cvta_generic_to_shared(sm);

    float acc[2][8][4];
#pragma unroll
    for (int i = 0; i < 2; i++)
#pragma unroll
        for (int j = 0; j < 8; j++)
#pragma unroll
            for (int k = 0; k < 4; k++) acc[i][j][k] = 0.f;

    auto load_stage = [&](int st, int kt) {
        uint32_t baseA = sb + st*GSTG*4;
        uint32_t baseB = baseA + 128*GP2*4;
#pragma unroll
        for (int it = 0; it < 4; it++) {
            int r = lr + it*32;
            cp_async16(baseA + r*GP2*4 + lc*16,
                       A + (size_t)(row0 + r)*DIM + kt*64 + lc*8);
            cp_async16(baseB + r*GP2*4 + lc*16,
                       W + (size_t)(col0 + r)*DIM + kt*64 + lc*8);
        }
        asm volatile("cp.async.commit_group;\n" ::);
    };

    const int T = DIM / 64;         // 6
    load_stage(0, 0);

    for (int tt = 0; tt < T; tt++) {
        if (tt + 1 < T) {
            load_stage((tt+1)&1, tt+1);
            asm volatile("cp.async.wait_group 1;\n" ::);
        } else {
            asm volatile("cp.async.wait_group 0;\n" ::);
        }
        __syncthreads();
        const uint32_t* Ab = sm + (tt&1)*GSTG;
        const uint32_t* Bb = Ab + 128*GP2;
#pragma unroll
        for (int kc = 0; kc < 4; kc++) {          // 4 x k16 chunks in 64-k slab
            int kq = kc*8 + t;
            uint32_t af[2][4], bf[8][2];
#pragma unroll
            for (int mt = 0; mt < 2; mt++) {
                int r = warp_m + mt*16 + g;
                af[mt][0] = Ab[(r   )*GP2 + kq];
                af[mt][1] = Ab[(r+8 )*GP2 + kq];
                af[mt][2] = Ab[(r   )*GP2 + kq+4];
                af[mt][3] = Ab[(r+8 )*GP2 + kq+4];
            }
#pragma unroll
            for (int nt = 0; nt < 8; nt++) {
                int c = warp_n + nt*8 + g;
                bf[nt][0] = Bb[c*GP2 + kq];
                bf[nt][1] = Bb[c*GP2 + kq+4];
            }
#pragma unroll
            for (int mt = 0; mt < 2; mt++)
#pragma unroll
                for (int nt = 0; nt < 8; nt++)
                    mma_f16(acc[mt][nt], af[mt], bf[nt]);
        }
        __syncthreads();
    }

#pragma unroll
    for (int mt = 0; mt < 2; mt++) {
#pragma unroll
        for (int nt = 0; nt < 8; nt++) {
            int nn0 = col0 + warp_n + nt*8 + 2*t;
#pragma unroll
            for (int rr = 0; rr < 2; rr++) {
                int m = row0 + warp_m + mt*16 + g + rr*8;
                float v0 = acc[mt][nt][rr*2+0] + bias[nn0];
                float v1 = acc[mt][nt][rr*2+1] + bias[nn0+1];
                if (QKV) {
                    int h  = nn0 / 96, cm = nn0 - h*96;
                    int seg = cm >> 5, c = cm & 31;
                    if (seg == 0) { v0 *= QK_SCALE; v1 *= QK_SCALE; }
                    int b_ = m / NT, n_ = m - b_*NT;
                    u16* dst = (seg == 0 ? g_q16 : (seg == 1 ? g_k16 : g_v16))
                               + ((size_t)(b_*HH + h)*NT + n_)*32 + c;
                    *(uint32_t*)dst = pack2(v0, v1);
                } else {
                    float2 o2 = {v0, v1};
                    *(float2*)(C + (size_t)m*DIM + nn0) = o2;
                }
            }
        }
    }
}

// ---------------- kernel 3: fp16 flash attention (no-max softmax) -------------
// Ksh pitch 20 half2 (per token: 16 half2 data), Vt pitch 108 half2 (token-pairs).
#define KP2 20
#define VP2 108
template<int NTC>
__device__ __forceinline__ void attn_chunk(int cb, const uint32_t qa[2][4],
                                           const float* gb0, const float* gb1,
                                           const uint32_t* Ksh, const uint32_t* Vt,
                                           int lane, float& l0, float& l1, float o[4][4]) {
    int g = lane >> 2, t = lane & 3;
    float s[NTC][4];
#pragma unroll
    for (int nt = 0; nt < NTC; nt++) { s[nt][0]=0.f; s[nt][1]=0.f; s[nt][2]=0.f; s[nt][3]=0.f; }
#pragma unroll
    for (int nt = 0; nt < NTC; nt++) {
        int m = cb + nt*8 + g;
#pragma unroll
        for (int kc = 0; kc < 2; kc++) {
            uint32_t bfr[2];
            bfr[0] = Ksh[m*KP2 + kc*8 + t];
            bfr[1] = Ksh[m*KP2 + kc*8 + t + 4];
            mma_f16(s[nt], qa[kc], bfr);
        }
    }
#pragma unroll
    for (int nt = 0; nt < NTC; nt++) {
        int cc = cb + nt*8 + 2*t;
        float2 b0 = *(const float2*)(gb0 + cc);
        float2 b1 = *(const float2*)(gb1 + cc);
        s[nt][0] = __expf(s[nt][0] + b0.x); l0 += s[nt][0];
        s[nt][1] = __expf(s[nt][1] + b0.y); l0 += s[nt][1];
        s[nt][2] = __expf(s[nt][2] + b1.x); l1 += s[nt][2];
        s[nt][3] = __expf(s[nt][3] + b1.y); l1 += s[nt][3];
    }
    // O += P V : P C-frag (c0,c1)=(tok 2t,2t+1) maps directly to fp16 A-frag
#pragma unroll
    for (int gi = 0; gi < NTC/2; gi++) {
        uint32_t pa[4];
        pa[0] = pack2(s[2*gi  ][0], s[2*gi  ][1]);
        pa[1] = pack2(s[2*gi  ][2], s[2*gi  ][3]);
        pa[2] = pack2(s[2*gi+1][0], s[2*gi+1][1]);
        pa[3] = pack2(s[2*gi+1][2], s[2*gi+1][3]);
        int jb = cb/2 + gi*8 + t;
#pragma unroll
        for (int vt = 0; vt < 4; vt++) {
            int d = vt*8 + g;
            uint32_t bfr[2];
            bfr[0] = Vt[d*VP2 + jb];
            bfr[1] = Vt[d*VP2 + jb + 4];
            mma_f16(o[vt], pa, bfr);
        }
    }
}

__global__ void __launch_bounds__(224, 2) attn_mma() {
    extern __shared__ uint32_t smu[];
    uint32_t* Ksh = smu;                 // [208][20] half2
    uint32_t* Vt  = smu + NP*KP2;        // [32][108] half2, (tok even, tok odd)

    int bh = blockIdx.x;
    int b_ = bh / HH;
    int h  = bh - b_*HH;
    int tid = threadIdx.x, w = tid >> 5, lane = tid & 31;
    int g = lane >> 2, t = lane & 3;

    // K: [tok][kd/2] half2
    for (int i = tid; i < NP*4; i += 224) {
        int m = i >> 2, c4 = i & 3;
        uint4 kv = {0u,0u,0u,0u};
        if (m < NT) kv = *(const uint4*)(g_k16 + ((size_t)bh*NT + m)*KD + c4*8);
        *(uint4*)&Ksh[m*KP2 + c4*4] = kv;
    }
    // V^T: Vt[d][j] = (V[2j][d], V[2j+1][d])
    for (int i = tid; i < 104*16; i += 224) {
        int j = i >> 4, d2 = i & 15;
        uint32_t va = 0u, vb = 0u;
        if (2*j < NT) {
            va = *(const uint32_t*)(g_v16 + ((size_t)bh*NT + 2*j  )*VD + d2*2);
            vb = *(const uint32_t*)(g_v16 + ((size_t)bh*NT + 2*j+1)*VD + d2*2);
        }
        half2 ha = *(half2*)&va, hb = *(half2*)&vb;
        half2 lo = __halves2half2(__low2half(ha),  __low2half(hb));
        half2 hi = __halves2half2(__high2half(ha), __high2half(hb));
        Vt[(2*d2  )*VP2 + j] = *(uint32_t*)&lo;
        Vt[(2*d2+1)*VP2 + j] = *(uint32_t*)&hi;
    }
    __syncthreads();

    for (int iter = 0; iter < 2; iter++) {
        int tile = w + iter*7;
        if (tile >= 13) break;
        int r0 = tile*16 + g;
        int r1 = r0 + 8;

        uint32_t qa[2][4];
        const u16* q0p = g_q16 + ((size_t)bh*NT + r0)*KD;
        const u16* q1p = g_q16 + ((size_t)bh*NT + r1)*KD;
#pragma unroll
        for (int kc = 0; kc < 2; kc++) {
            qa[kc][0] = (r0 < NT) ? *(const uint32_t*)(q0p + (kc*8 + t)*2)     : 0u;
            qa[kc][1] = (r1 < NT) ? *(const uint32_t*)(q1p + (kc*8 + t)*2)     : 0u;
            qa[kc][2] = (r0 < NT) ? *(const uint32_t*)(q0p + (kc*8 + t + 4)*2) : 0u;
            qa[kc][3] = (r1 < NT) ? *(const uint32_t*)(q1p + (kc*8 + t + 4)*2) : 0u;
        }

        const float* gb0 = g_b + ((size_t)h*NP + r0)*NP;
        const float* gb1 = g_b + ((size_t)h*NP + r1)*NP;

        float l0 = 0.f, l1 = 0.f;
        float o[4][4];
#pragma unroll
        for (int vt = 0; vt < 4; vt++) { o[vt][0]=0.f; o[vt][1]=0.f; o[vt][2]=0.f; o[vt][3]=0.f; }

        attn_chunk<14>(0,   qa, gb0, gb1, Ksh, Vt, lane, l0, l1, o);   // cols 0..111
        attn_chunk<12>(112, qa, gb0, gb1, Ksh, Vt, lane, l0, l1, o);   // cols 112..207

        l0 += __shfl_xor_sync(0xffffffffu, l0, 1);
        l0 += __shfl_xor_sync(0xffffffffu, l0, 2);
        l1 += __shfl_xor_sync(0xffffffffu, l1, 1);
        l1 += __shfl_xor_sync(0xffffffffu, l1, 2);
        float inv0 = __fdividef(1.f, l0);
        float inv1 = __fdividef(1.f, l1);

        if (r0 < NT) {
            u16* orow = g_att16 + ((size_t)(b_*NT + r0))*DIM + h*VD;
#pragma unroll
            for (int vt = 0; vt < 4; vt++)
                *(uint32_t*)(orow + vt*8 + 2*t) = pack2(o[vt][0]*inv0, o[vt][1]*inv0);
        }
        if (r1 < NT) {
            u16* orow = g_att16 + ((size_t)(b_*NT + r1))*DIM + h*VD;
#pragma unroll
            for (int vt = 0; vt < 4; vt++)
                *(uint32_t*)(orow + vt*8 + 2*t) = pack2(o[vt][2]*inv1, o[vt][3]*inv1);
        }
    }
}

// ---------------- launch ------------------------------------------------------
extern "C" void kernel_launch(void* const* d_in, const int* in_sizes, int n_in,
                              void* d_out, int out_size) {
    const float* x      = (const float*)d_in[0];
    const float* norm_w = (const float*)d_in[1];
    const float* norm_b = (const float*)d_in[2];
    const float* qkv_w  = (const float*)d_in[3];
    const float* qkv_b  = (const float*)d_in[4];
    const float* attb   = (const float*)d_in[5];
    const float* proj_w = (const float*)d_in[6];
    const float* proj_b = (const float*)d_in[7];
    const int*   bidx   = (const int*)  d_in[8];
    float* out = (float*)d_out;

    u16* qkvw16;  cudaGetSymbolAddress((void**)&qkvw16,  g_qkvw16);
    u16* projw16; cudaGetSymbolAddress((void**)&projw16, g_projw16);

    const int gemm_smem = 2 * GSTG * (int)sizeof(uint32_t);               // 73728
    const int attn_smem = (NP*KP2 + 32*VP2) * (int)sizeof(uint32_t);      // 30464
    cudaFuncSetAttribute(gemm_f16<true >, cudaFuncAttributeMaxDynamicSharedMemorySize, gemm_smem);
    cudaFuncSetAttribute(gemm_f16<false>, cudaFuncAttributeMaxDynamicSharedMemorySize, gemm_smem);
    cudaFuncSetAttribute(attn_mma,        cudaFuncAttributeMaxDynamicSharedMemorySize, attn_smem);

    cvt_f16_kernel<<<(FF*DIM/4 + 255)/256,  256>>>(qkv_w,  qkvw16,  FF*DIM/4);
    cvt_f16_kernel<<<(DIM*DIM/4 + 255)/256, 256>>>(proj_w, projw16, DIM*DIM/4);
    ln_kernel<<<MM/8, 256>>>(x, norm_w, norm_b);
    bias_expand<<<dim3(NP, HH), NP>>>(attb, bidx);
    gemm_f16<true ><<<dim3(FF/128,  MM/128), 256, gemm_smem>>>(qkvw16, qkv_b, nullptr);
    attn_mma<<<BB*HH, 224, attn_smem>>>();
    gemm_f16<false><<<dim3(DIM/128, MM/128), 256, gemm_smem>>>(projw16, proj_b, out);
}